// round 1
// baseline (speedup 1.0000x reference)
#include <cuda_runtime.h>

typedef unsigned long long u64;

// Precomputed layer gates: 8 gates (2 layers x 4 qubits), 12 splatted f32x2
// constants each: {u00r, -u00i, u00i, u01r, -u01i, u01i,
//                  u10r, -u10i, u10i, u11r, -u11i, u11i}
__device__ u64 d_gate[96];

// ---------- packed f32x2 helpers (Blackwell sm_100+) ----------
__device__ __forceinline__ u64 pk2(float a, float b) {
    u64 r; asm("mov.b64 %0,{%1,%2};" : "=l"(r) : "f"(a), "f"(b)); return r;
}
__device__ __forceinline__ float2 upk(u64 v) {
    float2 r; asm("mov.b64 {%0,%1},%2;" : "=f"(r.x), "=f"(r.y) : "l"(v)); return r;
}
__device__ __forceinline__ u64 fma2(u64 a, u64 b, u64 c) {
    u64 d; asm("fma.rn.f32x2 %0,%1,%2,%3;" : "=l"(d) : "l"(a), "l"(b), "l"(c)); return d;
}
__device__ __forceinline__ u64 mul2(u64 a, u64 b) {
    u64 d; asm("mul.rn.f32x2 %0,%1,%2;" : "=l"(d) : "l"(a), "l"(b)); return d;
}
__device__ __forceinline__ u64 add2(u64 a, u64 b) {
    u64 d; asm("add.rn.f32x2 %0,%1,%2;" : "=l"(d) : "l"(a), "l"(b)); return d;
}
// negation via sign-bit xor (ALU pipe, exact)
__device__ __forceinline__ u64 neg2(u64 a) {
    u64 r;
    asm("xor.b64 %0,%1,%2;" : "=l"(r) : "l"(a), "l"(0x8000000080000000ULL));
    return r;
}
__device__ __forceinline__ u64 sub2(u64 a, u64 b) { return add2(a, neg2(b)); }

// ---------- gate precompute: U = RZ(w2) * RY(w1) * RX(w0) ----------
__global__ void gate_precompute(const float* __restrict__ w) {
    int g = threadIdx.x;            // g = layer*4 + qubit
    if (g >= 8) return;
    float a = w[g * 3 + 0], b = w[g * 3 + 1], c = w[g * 3 + 2];
    float sa, ca, sb, cb, sg, cg;
    sincosf(0.5f * a, &sa, &ca);
    sincosf(0.5f * b, &sb, &cb);
    sincosf(0.5f * c, &sg, &cg);
    // M = RY * RX
    float m00r = cb * ca, m00i =  sb * sa;
    float m01r = -sb * ca, m01i = -cb * sa;
    float m10r =  sb * ca, m10i = -cb * sa;
    float m11r =  cb * ca, m11i = -sb * sa;
    // U = RZ * M : row0 *= (cg - i sg), row1 *= (cg + i sg)
    float u00r = cg * m00r + sg * m00i, u00i = cg * m00i - sg * m00r;
    float u01r = cg * m01r + sg * m01i, u01i = cg * m01i - sg * m01r;
    float u10r = cg * m10r - sg * m10i, u10i = cg * m10i + sg * m10r;
    float u11r = cg * m11r - sg * m11i, u11i = cg * m11i + sg * m11r;
    u64* t = d_gate + g * 12;
    t[0]  = pk2(u00r, u00r);  t[1]  = pk2(-u00i, -u00i);  t[2]  = pk2(u00i, u00i);
    t[3]  = pk2(u01r, u01r);  t[4]  = pk2(-u01i, -u01i);  t[5]  = pk2(u01i, u01i);
    t[6]  = pk2(u10r, u10r);  t[7]  = pk2(-u10i, -u10i);  t[8]  = pk2(u10i, u10i);
    t[9]  = pk2(u11r, u11r);  t[10] = pk2(-u11i, -u11i);  t[11] = pk2(u11i, u11i);
}

// Apply a 2x2 complex gate to one amplitude pair (both packed lines at once)
__device__ __forceinline__ void apply_pair(u64& r0, u64& i0, u64& r1, u64& i1,
                                           const u64 c[12]) {
    u64 ar0 = r0, ai0 = i0, ar1 = r1, ai1 = i1;
    r0 = fma2(c[4],  ai1, fma2(c[3], ar1, fma2(c[1], ai0, mul2(c[0], ar0))));
    i0 = fma2(c[5],  ar1, fma2(c[3], ai1, fma2(c[2], ar0, mul2(c[0], ai0))));
    r1 = fma2(c[10], ai1, fma2(c[9], ar1, fma2(c[7], ai0, mul2(c[6], ar0))));
    i1 = fma2(c[11], ar1, fma2(c[9], ai1, fma2(c[8], ar0, mul2(c[6], ai0))));
}

// Encoding for one qubit (two lines packed) followed by the layer-1 gate.
// RZ(pi*x0)|0> is a global phase -> dropped.
// u0 = cos(pi*x1/2) * e^{-i pi*x2/2},  u1 = sin(pi*x1/2) * e^{+i pi*x2/2}
__device__ __forceinline__ void enc_qubit(float x1a, float x2a, float x1b, float x2b,
                                          int n,
                                          u64& v0r, u64& v0i, u64& v1r, u64& v1i) {
    const float PIH = 1.57079632679489662f;
    float sb0, cb0, sg0, cg0, sb1, cb1, sg1, cg1;
    __sincosf(PIH * x1a, &sb0, &cb0);
    __sincosf(PIH * x2a, &sg0, &cg0);
    __sincosf(PIH * x1b, &sb1, &cb1);
    __sincosf(PIH * x2b, &sg1, &cg1);
    u64 u0r = pk2(cb0 * cg0, cb1 * cg1);
    u64 u0i = pk2(-cb0 * sg0, -cb1 * sg1);
    u64 u1r = pk2(sb0 * cg0, sb1 * cg1);
    u64 u1i = pk2(sb0 * sg0, sb1 * sg1);
    const u64* gp = d_gate + n * 12;
    u64 c[12];
#pragma unroll
    for (int k = 0; k < 12; k++) c[k] = __ldg(gp + k);
    v0r = fma2(c[4],  u1i, fma2(c[3], u1r, fma2(c[1], u0i, mul2(c[0], u0r))));
    v0i = fma2(c[5],  u1r, fma2(c[3], u1i, fma2(c[2], u0r, mul2(c[0], u0i))));
    v1r = fma2(c[10], u1i, fma2(c[9], u1r, fma2(c[7], u0i, mul2(c[6], u0r))));
    v1i = fma2(c[11], u1r, fma2(c[9], u1i, fma2(c[8], u0r, mul2(c[6], u0i))));
}

__global__ __launch_bounds__(256)
void qcnn_kernel(const float* __restrict__ x, float* __restrict__ out, int npair) {
    int t = blockIdx.x * blockDim.x + threadIdx.x;
    if (t >= npair) return;

    // two lines per thread: 24 contiguous floats = 6 float4 loads
    const float4* xb = (const float4*)(x + (size_t)t * 24);
    float4 A0 = __ldg(xb + 0), A1 = __ldg(xb + 1), A2 = __ldg(xb + 2);
    float4 A3 = __ldg(xb + 3), A4 = __ldg(xb + 4), A5 = __ldg(xb + 5);

    // per-qubit 2-vectors after encoding + layer-1 gate
    u64 a0r, a0i, a1r, a1i;  // qubit 0
    u64 b0r, b0i, b1r, b1i;  // qubit 1
    u64 c0r, c0i, c1r, c1i;  // qubit 2
    u64 d0r, d0i, d1r, d1i;  // qubit 3
    enc_qubit(A0.y, A0.z, A3.y, A3.z, 0, a0r, a0i, a1r, a1i);
    enc_qubit(A1.x, A1.y, A4.x, A4.y, 1, b0r, b0i, b1r, b1i);
    enc_qubit(A1.w, A2.x, A4.w, A5.x, 2, c0r, c0i, c1r, c1i);
    enc_qubit(A2.z, A2.w, A5.z, A5.w, 3, d0r, d0i, d1r, d1i);

    // pair01 = qubit0 (x) qubit1, with CZ(0,1) folded (negate [3])
    u64 p01r[4], p01i[4];
    {
        u64 nb0 = neg2(b0i), nb1 = neg2(b1i);
        p01r[0] = fma2(a0i, nb0, mul2(a0r, b0r)); p01i[0] = fma2(a0i, b0r, mul2(a0r, b0i));
        p01r[1] = fma2(a0i, nb1, mul2(a0r, b1r)); p01i[1] = fma2(a0i, b1r, mul2(a0r, b1i));
        p01r[2] = fma2(a1i, nb0, mul2(a1r, b0r)); p01i[2] = fma2(a1i, b0r, mul2(a1r, b0i));
        p01r[3] = neg2(fma2(a1i, nb1, mul2(a1r, b1r)));
        p01i[3] = neg2(fma2(a1i, b1r, mul2(a1r, b1i)));
    }
    // pair23 = qubit2 (x) qubit3, with CZ(2,3) folded (negate [3])
    u64 p23r[4], p23i[4];
    {
        u64 nd0 = neg2(d0i), nd1 = neg2(d1i);
        p23r[0] = fma2(c0i, nd0, mul2(c0r, d0r)); p23i[0] = fma2(c0i, d0r, mul2(c0r, d0i));
        p23r[1] = fma2(c0i, nd1, mul2(c0r, d1r)); p23i[1] = fma2(c0i, d1r, mul2(c0r, d1i));
        p23r[2] = fma2(c1i, nd0, mul2(c1r, d0r)); p23i[2] = fma2(c1i, d0r, mul2(c1r, d0i));
        p23r[3] = neg2(fma2(c1i, nd1, mul2(c1r, d1r)));
        p23i[3] = neg2(fma2(c1i, d1r, mul2(c1r, d1i)));
    }

    // full 16-amplitude state psi[p*4+q] = pair01[p] * pair23[q]
    u64 re[16], im[16];
    {
        u64 n23[4];
#pragma unroll
        for (int q = 0; q < 4; q++) n23[q] = neg2(p23i[q]);
#pragma unroll
        for (int p = 0; p < 4; p++) {
#pragma unroll
            for (int q = 0; q < 4; q++) {
                re[p * 4 + q] = fma2(p01i[p], n23[q], mul2(p01r[p], p23r[q]));
                im[p * 4 + q] = fma2(p01i[p], p23r[q], mul2(p01r[p], p23i[q]));
            }
        }
    }
    // CZ(1,2) from layer 1: negate where b1=b2=1 -> indices 6,7,14,15
    re[6]  = neg2(re[6]);  im[6]  = neg2(im[6]);
    re[7]  = neg2(re[7]);  im[7]  = neg2(im[7]);
    re[14] = neg2(re[14]); im[14] = neg2(im[14]);
    re[15] = neg2(re[15]); im[15] = neg2(im[15]);

    // ---- layer 2 single-qubit gates on full state ----
    // (layer-2 CZs are diagonal phases applied right before |.|^2 -> dropped)
    u64 c[12];
    {   // qubit 0: pairs (i, i+8)
        const u64* gp = d_gate + 4 * 12;
#pragma unroll
        for (int k = 0; k < 12; k++) c[k] = __ldg(gp + k);
#pragma unroll
        for (int i = 0; i < 8; i++)
            apply_pair(re[i], im[i], re[i + 8], im[i + 8], c);
    }
    {   // qubit 1: pairs (i, i+4), i in {0,1,2,3,8,9,10,11}
        const u64* gp = d_gate + 5 * 12;
#pragma unroll
        for (int k = 0; k < 12; k++) c[k] = __ldg(gp + k);
#pragma unroll
        for (int j = 0; j < 8; j++) {
            int i = ((j >> 2) << 3) | (j & 3);
            apply_pair(re[i], im[i], re[i + 4], im[i + 4], c);
        }
    }
    {   // qubit 2: pairs (i, i+2), i in {0,1,4,5,8,9,12,13}
        const u64* gp = d_gate + 6 * 12;
#pragma unroll
        for (int k = 0; k < 12; k++) c[k] = __ldg(gp + k);
#pragma unroll
        for (int j = 0; j < 8; j++) {
            int i = ((j >> 1) << 2) | (j & 1);
            apply_pair(re[i], im[i], re[i + 2], im[i + 2], c);
        }
    }
    {   // qubit 3: pairs (2i, 2i+1)
        const u64* gp = d_gate + 7 * 12;
#pragma unroll
        for (int k = 0; k < 12; k++) c[k] = __ldg(gp + k);
#pragma unroll
        for (int j = 0; j < 8; j++)
            apply_pair(re[2 * j], im[2 * j], re[2 * j + 1], im[2 * j + 1], c);
    }

    // probabilities + Z expectations (shared reduction tree)
    u64 p[16];
#pragma unroll
    for (int i = 0; i < 16; i++) p[i] = fma2(im[i], im[i], mul2(re[i], re[i]));

    // Z3: sign by lsb
    u64 Z3 = sub2(p[0], p[1]);
#pragma unroll
    for (int j = 1; j < 8; j++) Z3 = add2(Z3, sub2(p[2 * j], p[2 * j + 1]));
    u64 s2[8];
#pragma unroll
    for (int j = 0; j < 8; j++) s2[j] = add2(p[2 * j], p[2 * j + 1]);
    u64 Z2 = add2(add2(sub2(s2[0], s2[1]), sub2(s2[2], s2[3])),
                  add2(sub2(s2[4], s2[5]), sub2(s2[6], s2[7])));
    u64 s4[4];
#pragma unroll
    for (int k = 0; k < 4; k++) s4[k] = add2(s2[2 * k], s2[2 * k + 1]);
    u64 Z1 = add2(sub2(s4[0], s4[1]), sub2(s4[2], s4[3]));
    u64 Z0 = sub2(add2(s4[0], s4[1]), add2(s4[2], s4[3]));

    float2 z0 = upk(Z0), z1 = upk(Z1), z2 = upk(Z2), z3 = upk(Z3);
    float4* ob = (float4*)(out + (size_t)t * 8);
    ob[0] = make_float4(z0.x, z1.x, z2.x, z3.x);  // line 2t
    ob[1] = make_float4(z0.y, z1.y, z2.y, z3.y);  // line 2t+1
}

extern "C" void kernel_launch(void* const* d_in, const int* in_sizes, int n_in,
                              void* d_out, int out_size) {
    const float* x = (const float*)d_in[0];   // [128, 2048, 4, 3] f32
    const float* w = (const float*)d_in[1];   // [2, 4, 3] f32
    float* out = (float*)d_out;               // [128, 2048, 4] f32

    gate_precompute<<<1, 8>>>(w);

    int nlines = in_sizes[0] / 12;            // 262144
    int npair = nlines / 2;                   // 131072 threads, 2 lines each
    int block = 256;
    int grid = (npair + block - 1) / block;
    qcnn_kernel<<<grid, block>>>(x, out, npair);
}

// round 2
// speedup vs baseline: 1.9412x; 1.9412x over previous
#include <cuda_runtime.h>

typedef unsigned long long u64;

// ---------- packed f32x2 helpers (Blackwell sm_100+) ----------
__device__ __forceinline__ u64 pk2(float a, float b) {
    u64 r; asm("mov.b64 %0,{%1,%2};" : "=l"(r) : "f"(a), "f"(b)); return r;
}
__device__ __forceinline__ float2 upk(u64 v) {
    float2 r; asm("mov.b64 {%0,%1},%2;" : "=f"(r.x), "=f"(r.y) : "l"(v)); return r;
}
__device__ __forceinline__ u64 fma2(u64 a, u64 b, u64 c) {
    u64 d; asm("fma.rn.f32x2 %0,%1,%2,%3;" : "=l"(d) : "l"(a), "l"(b), "l"(c)); return d;
}
__device__ __forceinline__ u64 mul2(u64 a, u64 b) {
    u64 d; asm("mul.rn.f32x2 %0,%1,%2;" : "=l"(d) : "l"(a), "l"(b)); return d;
}
__device__ __forceinline__ u64 add2(u64 a, u64 b) {
    u64 d; asm("add.rn.f32x2 %0,%1,%2;" : "=l"(d) : "l"(a), "l"(b)); return d;
}
__device__ __forceinline__ u64 neg2(u64 a) {
    u64 r; asm("xor.b64 %0,%1,%2;" : "=l"(r) : "l"(a), "l"(0x8000000080000000ULL));
    return r;
}
__device__ __forceinline__ u64 sub2(u64 a, u64 b) { return add2(a, neg2(b)); }

// Encoding for one qubit (two lines packed) followed by its layer-1 gate.
// RZ(pi*x0)|0> is a global phase -> dropped (cancels in all |.|^2 and
// conj-cross terms).  u0 = cos(pi*x1/2) e^{-i pi*x2/2}, u1 = sin(..) e^{+i..}
__device__ __forceinline__ void enc_qubit(float x1a, float x2a, float x1b, float x2b,
                                          const u64* __restrict__ c,
                                          u64& v0r, u64& v0i, u64& v1r, u64& v1i) {
    const float PIH = 1.57079632679489662f;
    float sb0, cb0, sg0, cg0, sb1, cb1, sg1, cg1;
    __sincosf(PIH * x1a, &sb0, &cb0);
    __sincosf(PIH * x2a, &sg0, &cg0);
    __sincosf(PIH * x1b, &sb1, &cb1);
    __sincosf(PIH * x2b, &sg1, &cg1);
    u64 u0r = pk2(cb0 * cg0, cb1 * cg1);
    u64 u0i = pk2(-cb0 * sg0, -cb1 * sg1);
    u64 u1r = pk2(sb0 * cg0, sb1 * cg1);
    u64 u1i = pk2(sb0 * sg0, sb1 * sg1);
    // gate constants c[12] = {u00r,-u00i,u00i, u01r,-u01i,u01i,
    //                         u10r,-u10i,u10i, u11r,-u11i,u11i} (splatted)
    v0r = fma2(c[4],  u1i, fma2(c[3], u1r, fma2(c[1], u0i, mul2(c[0], u0r))));
    v0i = fma2(c[5],  u1r, fma2(c[3], u1i, fma2(c[2], u0r, mul2(c[0], u0i))));
    v1r = fma2(c[10], u1i, fma2(c[9], u1r, fma2(c[7], u0i, mul2(c[6], u0r))));
    v1i = fma2(c[11], u1r, fma2(c[9], u1i, fma2(c[8], u0r, mul2(c[6], u0i))));
}

__global__ __launch_bounds__(256)
void qcnn_kernel(const float* __restrict__ x, const float* __restrict__ w,
                 float* __restrict__ out, int npair) {
    // sg: 4 layer-1 gates x 12 splatted f32x2 constants
    // sm: 4 measurement observables x {a, 2b, -2c} splatted
    __shared__ u64 sg[48];
    __shared__ u64 sm[12];

    int tid = threadIdx.x;
    if (tid < 8) {
        int h = tid >> 2, q = tid & 3;
        const float* wp = w + h * 12 + q * 3;
        float a = wp[0], b = wp[1], g = wp[2];
        float sa, ca, sb, cb, sgg, cgg;
        sincosf(0.5f * a, &sa, &ca);
        sincosf(0.5f * b, &sb, &cb);
        sincosf(0.5f * g, &sgg, &cgg);
        // M = RY * RX
        float m00r = cb * ca, m00i =  sb * sa;
        float m01r = -sb * ca, m01i = -cb * sa;
        float m10r =  sb * ca, m10i = -cb * sa;
        float m11r =  cb * ca, m11i = -sb * sa;
        // U = RZ * M
        float u00r = cgg * m00r + sgg * m00i, u00i = cgg * m00i - sgg * m00r;
        float u01r = cgg * m01r + sgg * m01i, u01i = cgg * m01i - sgg * m01r;
        float u10r = cgg * m10r - sgg * m10i, u10i = cgg * m10i + sgg * m10r;
        float u11r = cgg * m11r - sgg * m11i, u11i = cgg * m11i + sgg * m11r;
        if (h == 0) {
            u64* t = sg + q * 12;
            t[0]  = pk2(u00r, u00r);  t[1]  = pk2(-u00i, -u00i);  t[2]  = pk2(u00i, u00i);
            t[3]  = pk2(u01r, u01r);  t[4]  = pk2(-u01i, -u01i);  t[5]  = pk2(u01i, u01i);
            t[6]  = pk2(u10r, u10r);  t[7]  = pk2(-u10i, -u10i);  t[8]  = pk2(u10i, u10i);
            t[9]  = pk2(u11r, u11r);  t[10] = pk2(-u11i, -u11i);  t[11] = pk2(u11i, u11i);
        } else {
            // M_q = U^dag Z U = [[a, b+ic],[b-ic, -a]]
            float ma = u00r * u00r + u00i * u00i - u10r * u10r - u10i * u10i;
            float mb = u00r * u01r + u00i * u01i - (u10r * u11r + u10i * u11i);
            float mc = u00r * u01i - u00i * u01r - (u10r * u11i - u10i * u11r);
            sm[q * 3 + 0] = pk2(ma, ma);
            sm[q * 3 + 1] = pk2(2.f * mb, 2.f * mb);
            sm[q * 3 + 2] = pk2(-2.f * mc, -2.f * mc);
        }
    }
    __syncthreads();

    int t = blockIdx.x * blockDim.x + threadIdx.x;
    if (t >= npair) return;

    // two lines per thread: 24 contiguous floats = 6 float4 loads
    const float4* xb = (const float4*)(x + (size_t)t * 24);
    float4 A0 = __ldg(xb + 0), A1 = __ldg(xb + 1), A2 = __ldg(xb + 2);
    float4 A3 = __ldg(xb + 3), A4 = __ldg(xb + 4), A5 = __ldg(xb + 5);

    // per-qubit 2-vectors after encoding + layer-1 gate
    u64 a0r, a0i, a1r, a1i;  // qubit 0
    u64 b0r, b0i, b1r, b1i;  // qubit 1
    u64 c0r, c0i, c1r, c1i;  // qubit 2
    u64 d0r, d0i, d1r, d1i;  // qubit 3
    enc_qubit(A0.y, A0.z, A3.y, A3.z, sg + 0,  a0r, a0i, a1r, a1i);
    enc_qubit(A1.x, A1.y, A4.x, A4.y, sg + 12, b0r, b0i, b1r, b1i);
    enc_qubit(A1.w, A2.x, A4.w, A5.x, sg + 24, c0r, c0i, c1r, c1i);
    enc_qubit(A2.z, A2.w, A5.z, A5.w, sg + 36, d0r, d0i, d1r, d1i);

    // u = qubit0 (x) qubit1 with CZ(0,1) folded (u3 negated)
    u64 u0r_, u0i_, u1r_, u1i_, u2r_, u2i_, u3r_, u3i_;
    {
        u64 nb0 = neg2(b0i), nb1 = neg2(b1i);
        u0r_ = fma2(a0i, nb0, mul2(a0r, b0r)); u0i_ = fma2(a0i, b0r, mul2(a0r, b0i));
        u1r_ = fma2(a0i, nb1, mul2(a0r, b1r)); u1i_ = fma2(a0i, b1r, mul2(a0r, b1i));
        u2r_ = fma2(a1i, nb0, mul2(a1r, b0r)); u2i_ = fma2(a1i, b0r, mul2(a1r, b0i));
        u3r_ = neg2(fma2(a1i, nb1, mul2(a1r, b1r)));
        u3i_ = neg2(fma2(a1i, b1r, mul2(a1r, b1i)));
    }
    // v = qubit2 (x) qubit3 with CZ(2,3) folded (v3 negated)
    u64 v0r_, v0i_, v1r_, v1i_, v2r_, v2i_, v3r_, v3i_;
    {
        u64 nd0 = neg2(d0i), nd1 = neg2(d1i);
        v0r_ = fma2(c0i, nd0, mul2(c0r, d0r)); v0i_ = fma2(c0i, d0r, mul2(c0r, d0i));
        v1r_ = fma2(c0i, nd1, mul2(c0r, d1r)); v1i_ = fma2(c0i, d1r, mul2(c0r, d1i));
        v2r_ = fma2(c1i, nd0, mul2(c1r, d0r)); v2i_ = fma2(c1i, d0r, mul2(c1r, d0i));
        v3r_ = neg2(fma2(c1i, nd1, mul2(c1r, d1r)));
        v3i_ = neg2(fma2(c1i, d1r, mul2(c1r, d1i)));
    }

    // ---- measurement: psi1 = CZ(1,2) (u (x) v); 16-amp state never formed ----
    // probabilities of pair amps
    u64 Pu0 = fma2(u0i_, u0i_, mul2(u0r_, u0r_));
    u64 Pu1 = fma2(u1i_, u1i_, mul2(u1r_, u1r_));
    u64 Pu2 = fma2(u2i_, u2i_, mul2(u2r_, u2r_));
    u64 Pu3 = fma2(u3i_, u3i_, mul2(u3r_, u3r_));
    u64 Pv0 = fma2(v0i_, v0i_, mul2(v0r_, v0r_));
    u64 Pv1 = fma2(v1i_, v1i_, mul2(v1r_, v1r_));
    u64 Pv2 = fma2(v2i_, v2i_, mul2(v2r_, v2r_));
    u64 Pv3 = fma2(v3i_, v3i_, mul2(v3r_, v3r_));
    // diagonal-Z combos (pair norms are 1, so the other factor drops out)
    u64 Du0 = sub2(add2(Pu0, Pu1), add2(Pu2, Pu3));
    u64 Du1 = add2(sub2(Pu0, Pu1), sub2(Pu2, Pu3));
    u64 Dv2 = sub2(add2(Pv0, Pv1), add2(Pv2, Pv3));
    u64 Dv3 = add2(sub2(Pv0, Pv1), sub2(Pv2, Pv3));

    // cross terms X_i (CZ(1,2) sign structure already accounted for:
    // Z1/Z2 cross parts get scaled by Dv2/Du1 respectively)
    // X0 = conj(u0)u2 + conj(u1)u3
    u64 ReX0 = fma2(u1i_, u3i_, fma2(u1r_, u3r_, fma2(u0i_, u2i_, mul2(u0r_, u2r_))));
    u64 ImX0 = fma2(u1r_, u3i_, fma2(u0r_, u2i_,
               neg2(fma2(u1i_, u3r_, mul2(u0i_, u2r_)))));
    // X1 = conj(u0)u1 + conj(u2)u3
    u64 ReX1 = fma2(u2i_, u3i_, fma2(u2r_, u3r_, fma2(u0i_, u1i_, mul2(u0r_, u1r_))));
    u64 ImX1 = fma2(u2r_, u3i_, fma2(u0r_, u1i_,
               neg2(fma2(u2i_, u3r_, mul2(u0i_, u1r_)))));
    // X2 = conj(v0)v2 + conj(v1)v3
    u64 ReX2 = fma2(v1i_, v3i_, fma2(v1r_, v3r_, fma2(v0i_, v2i_, mul2(v0r_, v2r_))));
    u64 ImX2 = fma2(v1r_, v3i_, fma2(v0r_, v2i_,
               neg2(fma2(v1i_, v3r_, mul2(v0i_, v2r_)))));
    // X3 = conj(v0)v1 + conj(v2)v3
    u64 ReX3 = fma2(v2i_, v3i_, fma2(v2r_, v3r_, fma2(v0i_, v1i_, mul2(v0r_, v1r_))));
    u64 ImX3 = fma2(v2r_, v3i_, fma2(v0r_, v1i_,
               neg2(fma2(v2i_, v3r_, mul2(v0i_, v1r_)))));

    // Z_i = a_i * D_i + (2b_i * ReX_i - 2c_i * ImX_i) [* D-factor for 1,2]
    u64 Z0 = fma2(sm[2],  ImX0, fma2(sm[1],  ReX0, mul2(sm[0], Du0)));
    u64 Z1 = fma2(fma2(sm[5], ImX1, mul2(sm[4], ReX1)), Dv2, mul2(sm[3], Du1));
    u64 Z2 = fma2(fma2(sm[8], ImX2, mul2(sm[7], ReX2)), Du1, mul2(sm[6], Dv2));
    u64 Z3 = fma2(sm[11], ImX3, fma2(sm[10], ReX3, mul2(sm[9], Dv3)));

    float2 z0 = upk(Z0), z1 = upk(Z1), z2 = upk(Z2), z3 = upk(Z3);
    float4* ob = (float4*)(out + (size_t)t * 8);
    ob[0] = make_float4(z0.x, z1.x, z2.x, z3.x);  // line 2t
    ob[1] = make_float4(z0.y, z1.y, z2.y, z3.y);  // line 2t+1
}

extern "C" void kernel_launch(void* const* d_in, const int* in_sizes, int n_in,
                              void* d_out, int out_size) {
    const float* x = (const float*)d_in[0];   // [128, 2048, 4, 3] f32
    const float* w = (const float*)d_in[1];   // [2, 4, 3] f32
    float* out = (float*)d_out;               // [128, 2048, 4] f32

    int nlines = in_sizes[0] / 12;            // 262144
    int npair = nlines / 2;                   // 131072 threads, 2 lines each
    int block = 256;
    int grid = (npair + block - 1) / block;
    qcnn_kernel<<<grid, block>>>(x, w, out, npair);
}